// round 16
// baseline (speedup 1.0000x reference)
#include <cuda_runtime.h>
#include <cuda_bf16.h>
#include <cstdint>

#define BATCH 1024
#define MDIM  1024
#define NDIM  512
#define LAMBD 0.2f
#define TOLC  1e-4f
#define MAX_ITERS 100
#define GRID  128
#define NTHR  512
#define NSTAGE 24            // loop: half of (3 terms x 16 k64-chunks)
#define PIPE  4

// dynamic smem layout (bytes)
#define SM_RED   64         // 32 floats
#define SM_CONV  192        // 4 ints
#define SM_SCAN  256        // 16 ints (warp totals)
#define SM_ACT   2560       // 1024 ints
#define SM_A0    8192       // A stage buffers 4 x 16KB
#define SM_B0    73728      // B stage buffers 4 x 16KB
#define SMEM_TOTAL 139264

__device__ __align__(16) float g_s[BATCH * MDIM];            // Adotb (constant)
__device__ __align__(16) float g_y[BATCH * MDIM];            // y = xk + u (pre-shrink)
__device__ __align__(16) float g_vsol[BATCH * MDIM];
__device__ __align__(16) float g_xkA[BATCH * MDIM];
__device__ __align__(16) float g_xkB[BATCH * MDIM];
__device__ __align__(16) __nv_bfloat16 g_Eh[BATCH * MDIM];
__device__ __align__(16) __nv_bfloat16 g_Em[BATCH * MDIM];
__device__ __align__(16) __nv_bfloat16 g_Vh[BATCH * MDIM];   // splits of vsol
__device__ __align__(16) __nv_bfloat16 g_Vm[BATCH * MDIM];
__device__ __align__(16) __nv_bfloat16 g_Bh[MDIM * MDIM];    // B[n][k] = Minv[k][n]
__device__ __align__(16) __nv_bfloat16 g_Bm[MDIM * MDIM];
__device__ __align__(16) __nv_bfloat16 g_Wh[NDIM * MDIM];    // W[n][k] = w[k][n] (decode)
__device__ __align__(16) __nv_bfloat16 g_Wm[NDIM * MDIM];
__device__ __align__(16) __nv_bfloat16 g_Xh[BATCH * NDIM];   // splits of x (Phase A)
__device__ __align__(16) __nv_bfloat16 g_Xm[BATCH * NDIM];
__device__ __align__(16) __nv_bfloat16 g_wh2[MDIM * NDIM];   // splits of w, K-major
__device__ __align__(16) __nv_bfloat16 g_wm2[MDIM * NDIM];
__device__ int g_flag[BATCH];
__device__ int g_arrive[GRID * 32];                           // one 128B line per CTA
__device__ unsigned g_release;

// ---------- helpers ----------
__device__ __forceinline__ uint32_t smem_u32(const void* p) {
    uint32_t a;
    asm("{ .reg .u64 t; cvta.to.shared.u64 t, %1; cvt.u32.u64 %0, t; }" : "=r"(a) : "l"(p));
    return a;
}
__device__ __forceinline__ uint32_t swz(uint32_t o) { return o ^ ((o >> 3) & 0x70); }

__device__ __forceinline__ void cp16(uint32_t d, const void* s) {
    asm volatile("cp.async.cg.shared.global [%0], [%1], 16;" :: "r"(d), "l"(s));
}
__device__ __forceinline__ void cp_commit() { asm volatile("cp.async.commit_group;" ::: "memory"); }
template <int N> __device__ __forceinline__ void cp_wait() {
    asm volatile("cp.async.wait_group %0;" :: "n"(N) : "memory");
}
__device__ __forceinline__ void ldsm_x4(uint32_t& r0, uint32_t& r1, uint32_t& r2,
                                        uint32_t& r3, uint32_t a) {
    asm volatile("ldmatrix.sync.aligned.m8n8.x4.shared.b16 {%0,%1,%2,%3}, [%4];"
                 : "=r"(r0), "=r"(r1), "=r"(r2), "=r"(r3) : "r"(a));
}
__device__ __forceinline__ void ldsm_x2t(uint32_t& r0, uint32_t& r1, uint32_t a) {
    asm volatile("ldmatrix.sync.aligned.m8n8.x2.trans.shared.b16 {%0,%1}, [%2];"
                 : "=r"(r0), "=r"(r1) : "r"(a));
}
__device__ __forceinline__ void mma16816(float d[4], const uint32_t a[4], const uint32_t b[2]) {
    asm volatile(
        "mma.sync.aligned.m16n8k16.row.col.f32.bf16.bf16.f32 "
        "{%0,%1,%2,%3}, {%4,%5,%6,%7}, {%8,%9}, {%0,%1,%2,%3};"
        : "+f"(d[0]), "+f"(d[1]), "+f"(d[2]), "+f"(d[3])
        : "r"(a[0]), "r"(a[1]), "r"(a[2]), "r"(a[3]), "r"(b[0]), "r"(b[1]));
}

// flag-based grid barrier: parallel arrivals (distinct lines) + single release word
__device__ __forceinline__ void gridbar(unsigned& epoch) {
    epoch++;
    __syncthreads();
    const int tid = threadIdx.x;
    if (tid == 0) {
        __threadfence();
        *(volatile int*)&g_arrive[blockIdx.x * 32] = (int)epoch;
    }
    if (blockIdx.x == 0) {
        if (tid < GRID) {
            while (*(volatile int*)&g_arrive[tid * 32] != (int)epoch) {}
        }
        __syncthreads();
        if (tid == 0) {
            __threadfence();
            *(volatile unsigned*)&g_release = epoch;
        }
    }
    if (tid == 0) {
        while (*(volatile unsigned*)&g_release != epoch) {}
        __threadfence();
    }
    __syncthreads();
}

__device__ __forceinline__ float sshrink(float x) {
    return x > LAMBD ? x - LAMBD : (x < -LAMBD ? x + LAMBD : 0.f);
}
__device__ __forceinline__ void split2(float a, __nv_bfloat16& h, __nv_bfloat16& m) {
    h = __float2bfloat16(a);
    m = __float2bfloat16(a - __bfloat162float(h));
}

// init + bf16 splits of x and w (K-major, Phase A) fused
__global__ void k_init(const float* __restrict__ x, const float* __restrict__ w) {
    int tid = blockIdx.x * blockDim.x + threadIdx.x, nt = gridDim.x * blockDim.x;
    float4 z = make_float4(0.f, 0.f, 0.f, 0.f);
    for (int i = tid; i < BATCH * MDIM / 4; i += nt) {
        ((float4*)g_y)[i] = z; ((float4*)g_vsol)[i] = z;
    }
    uint4 z4 = make_uint4(0u, 0u, 0u, 0u);
    for (int i = tid; i < BATCH * MDIM / 8; i += nt) {
        ((uint4*)g_Vh)[i] = z4; ((uint4*)g_Vm)[i] = z4;
    }
    for (int i = tid; i < BATCH; i += nt) g_flag[i] = 0;
    for (int i = tid; i < GRID * 32; i += nt) g_arrive[i] = 0;
    if (tid == 0) g_release = 0u;
    for (int i = tid; i < BATCH * NDIM / 4; i += nt) {
        float4 a = ((const float4*)x)[i];
        float4 b = ((const float4*)w)[i];
        __align__(8) __nv_bfloat16 h[4], m[4];
        split2(a.x, h[0], m[0]); split2(a.y, h[1], m[1]);
        split2(a.z, h[2], m[2]); split2(a.w, h[3], m[3]);
        ((uint2*)g_Xh)[i] = *(uint2*)h; ((uint2*)g_Xm)[i] = *(uint2*)m;
        split2(b.x, h[0], m[0]); split2(b.y, h[1], m[1]);
        split2(b.z, h[2], m[2]); split2(b.w, h[3], m[3]);
        ((uint2*)g_wh2)[i] = *(uint2*)h; ((uint2*)g_wm2)[i] = *(uint2*)m;
    }
}

// transpose + 2-way bf16 split of Minv (1024x1024)
__global__ void k_prep(const float* __restrict__ Minv) {
    __shared__ float t[32][33];
    int tx = threadIdx.x, ty = threadIdx.y, nt = blockIdx.x, kt = blockIdx.y;
#pragma unroll
    for (int i = 0; i < 4; ++i)
        t[ty + 8 * i][tx] = Minv[(kt * 32 + ty + 8 * i) * MDIM + nt * 32 + tx];
    __syncthreads();
#pragma unroll
    for (int i = 0; i < 4; ++i) {
        int n = nt * 32 + ty + 8 * i, k = kt * 32 + tx;
        __nv_bfloat16 h, m;
        split2(t[tx][ty + 8 * i], h, m);
        g_Bh[n * MDIM + k] = h; g_Bm[n * MDIM + k] = m;
    }
}

// transpose + 2-way bf16 split of w (1024x512) -> W[n][k] (for decode)
__global__ void k_prepw(const float* __restrict__ w) {
    __shared__ float t[32][33];
    int tx = threadIdx.x, ty = threadIdx.y, nt = blockIdx.x, kt = blockIdx.y;
#pragma unroll
    for (int i = 0; i < 4; ++i)
        t[ty + 8 * i][tx] = w[(kt * 32 + ty + 8 * i) * NDIM + nt * 32 + tx];
    __syncthreads();
#pragma unroll
    for (int i = 0; i < 4; ++i) {
        int n = nt * 32 + ty + 8 * i, k = kt * 32 + tx;
        __nv_bfloat16 h, m;
        split2(t[tx][ty + 8 * i], h, m);
        g_Wh[n * MDIM + k] = h; g_Wm[n * MDIM + k] = m;
    }
}

// shared HMMA mainloop: 128x128 tile, 512 threads (16 warps, 32x32 warp tiles),
// nst k64 stages, 4-deep cp.async pipe, one __syncthreads per stage.
// Schedule: global stage g -> term g>>KSH, k0 = (g & ((1<<KSH)-1))*64.
template <int KSH>
__device__ __forceinline__ void hmma_tile(
    uint32_t smb, int gbase, int nst,
    const __nv_bfloat16* TA0, const __nv_bfloat16* TA1, const __nv_bfloat16* TA2,
    const __nv_bfloat16* TB0, const __nv_bfloat16* TB1, const __nv_bfloat16* TB2,
    const int aoff[2], const int boff[2], const uint32_t dsw[2],
    const uint32_t offA[2], const uint32_t offB[4], float acc[2][4][4]) {
    const __nv_bfloat16* TA[3] = {TA0, TA1, TA2};
    const __nv_bfloat16* TB[3] = {TB0, TB1, TB2};
    const int KM = (1 << KSH) - 1;
#pragma unroll
    for (int p = 0; p < PIPE - 1; ++p) {
        int g = gbase + p, t2 = g >> KSH, k2 = (g & KM) * 64;
        uint32_t ab = smb + SM_A0 + p * 16384, bb = smb + SM_B0 + p * 16384;
#pragma unroll
        for (int c = 0; c < 2; ++c) {
            cp16(ab + dsw[c], TA[t2] + aoff[c] + k2);
            cp16(bb + dsw[c], TB[t2] + boff[c] + k2);
        }
        cp_commit();
    }
    for (int s = 0; s < nst; ++s) {
        cp_wait<PIPE - 2>();
        __syncthreads();
        if (s + PIPE - 1 < nst) {
            int nb = (s + PIPE - 1) & (PIPE - 1);
            int g = gbase + s + PIPE - 1, t2 = g >> KSH, k2 = (g & KM) * 64;
            uint32_t ab = smb + SM_A0 + nb * 16384, bb = smb + SM_B0 + nb * 16384;
#pragma unroll
            for (int c = 0; c < 2; ++c) {
                cp16(ab + dsw[c], TA[t2] + aoff[c] + k2);
                cp16(bb + dsw[c], TB[t2] + boff[c] + k2);
            }
        }
        cp_commit();   // always commit (possibly empty) to keep wait-count semantics
        int buf = s & (PIPE - 1);
        uint32_t Ab = smb + SM_A0 + buf * 16384;
        uint32_t Bb = smb + SM_B0 + buf * 16384;
#pragma unroll
        for (int kk = 0; kk < 4; ++kk) {
            uint32_t kx = (uint32_t)(kk << 5);
            uint32_t af[2][4], bf[4][2];
#pragma unroll
            for (int mi = 0; mi < 2; ++mi)
                ldsm_x4(af[mi][0], af[mi][1], af[mi][2], af[mi][3], Ab + (offA[mi] ^ kx));
#pragma unroll
            for (int ni = 0; ni < 4; ++ni)
                ldsm_x2t(bf[ni][0], bf[ni][1], Bb + (offB[ni] ^ kx));
#pragma unroll
            for (int mi = 0; mi < 2; ++mi)
#pragma unroll
                for (int ni = 0; ni < 4; ++ni)
                    mma16816(acc[mi][ni], af[mi], bf[ni]);
        }
    }
    cp_wait<0>();
}

__global__ void __launch_bounds__(NTHR, 1)
k_admm(const float* __restrict__ x, const float* __restrict__ w) {
    extern __shared__ char sm[];
    const uint32_t smb = smem_u32(sm);
    const int tid = threadIdx.x;
    const int lane = tid & 31, wrp = tid >> 5;
    unsigned bar_epoch = 0;

    int* s_scan = (int*)(sm + SM_SCAN);
    int* s_act = (int*)(sm + SM_ACT);
    float* s_red = (float*)(sm + SM_RED);
    int* s_conv = (int*)(sm + SM_CONV);

    // per-lane ldmatrix offsets (shared by all HMMA phases)
    const int wm = wrp >> 2, wn = wrp & 3;
    const int rowa = wm * 32 + (lane & 7) + ((lane >> 3) & 1) * 8;
    const int qa = lane >> 4;
    uint32_t offA[2];
#pragma unroll
    for (int mi = 0; mi < 2; ++mi)
        offA[mi] = swz((uint32_t)((rowa + mi * 16) * 128 + qa * 16));
    const int rowb = wn * 32 + (lane & 7);
    const int qb = (lane >> 3) & 1;
    uint32_t offB[4];
#pragma unroll
    for (int ni = 0; ni < 4; ++ni)
        offB[ni] = swz((uint32_t)((rowb + ni * 8) * 128 + qb * 16));
    uint32_t dsw[2];
    int rw_[2], q_[2];
#pragma unroll
    for (int c = 0; c < 2; ++c) {
        int idx = tid + 512 * c;
        rw_[c] = idx >> 3; q_[c] = idx & 7;
        dsw[c] = swz((uint32_t)(rw_[c] * 128 + q_[c] * 16));
    }

    // ===== Phase A: s = x @ w^T via HMMA 3-term split (K=512, 2-way K-split) =====
    {
        int unit = blockIdx.x & 63, ks = blockIdx.x >> 6;
        int tm = unit >> 3, tn = unit & 7;
        int aoff[2], boff[2];
#pragma unroll
        for (int c = 0; c < 2; ++c) {
            aoff[c] = (tm * 128 + rw_[c]) * NDIM + q_[c] * 8;
            boff[c] = (tn * 128 + rw_[c]) * NDIM + q_[c] * 8;
        }
        float acc[2][4][4];
#pragma unroll
        for (int mi = 0; mi < 2; ++mi)
#pragma unroll
            for (int ni = 0; ni < 4; ++ni)
#pragma unroll
                for (int q = 0; q < 4; ++q) acc[mi][ni][q] = 0.f;

        hmma_tile<3>(smb, ks * 12, 12, g_Xh, g_Xh, g_Xm, g_wh2, g_wm2, g_wh2,
                     aoff, boff, dsw, offA, offB, acc);

        float* dst = ks ? g_xkB : g_xkA;
        int cbase = tn * 128 + wn * 32 + 2 * (lane & 3);
#pragma unroll
        for (int mi = 0; mi < 2; ++mi)
#pragma unroll
            for (int half = 0; half < 2; ++half) {
                int row = tm * 128 + wm * 32 + mi * 16 + (lane >> 2) + half * 8;
                float* p = dst + row * MDIM + cbase;
#pragma unroll
                for (int ni = 0; ni < 4; ++ni)
                    *(float2*)(p + ni * 8) = make_float2(acc[mi][ni][half * 2],
                                                         acc[mi][ni][half * 2 + 1]);
            }
    }
    gridbar(bar_epoch);
    // sum partials -> s, initial E splits (v=u=0 -> E=s)
    {
        for (int i = blockIdx.x * NTHR + tid; i < BATCH * MDIM / 4; i += GRID * NTHR) {
            float4 a = __ldcg((const float4*)g_xkA + i);
            float4 b = __ldcg((const float4*)g_xkB + i);
            float4 sv = make_float4(a.x + b.x, a.y + b.y, a.z + b.z, a.w + b.w);
            ((float4*)g_s)[i] = sv;
            __align__(8) __nv_bfloat16 h[4], m[4];
            split2(sv.x, h[0], m[0]); split2(sv.y, h[1], m[1]);
            split2(sv.z, h[2], m[2]); split2(sv.w, h[3], m[3]);
            ((uint2*)g_Eh)[i] = *(uint2*)h;
            ((uint2*)g_Em)[i] = *(uint2*)m;
        }
    }
    gridbar(bar_epoch);

    // ===== ADMM loop =====
    for (int it = 0; it < MAX_ITERS; ++it) {
        // shuffle-based ordered compaction of active rows (2 flags/thread)
        int fl[2], cnt = 0;
#pragma unroll
        for (int j = 0; j < 2; ++j) { fl[j] = g_flag[tid * 2 + j]; cnt += (fl[j] == 0); }
        int inc = cnt;
#pragma unroll
        for (int o = 1; o < 32; o <<= 1) {
            int nv = __shfl_up_sync(0xffffffffu, inc, o);
            if (lane >= o) inc += nv;
        }
        if (lane == 31) s_scan[wrp] = inc;
        __syncthreads();
        if (wrp == 0) {
            int v = (lane < 16) ? s_scan[lane] : 0;
#pragma unroll
            for (int o = 1; o < 16; o <<= 1) {
                int nv = __shfl_up_sync(0xffffffffu, v, o);
                if (lane >= o) v += nv;
            }
            if (lane < 16) s_scan[lane] = v;
        }
        __syncthreads();
        int base = (wrp ? s_scan[wrp - 1] : 0) + inc - cnt;
#pragma unroll
        for (int j = 0; j < 2; ++j)
            if (!fl[j]) s_act[base++] = tid * 2 + j;
        int nact = s_scan[15];
        __syncthreads();
        if (nact == 0) break;
        int ntm = (nact + 127) >> 7;

        // ---- HMMA GEMM: xk partials over 3 bf16-split terms (hh, hm, mh) ----
        int unit = blockIdx.x & 63, ks = blockIdx.x >> 6;
        int tm = unit >> 3, tn = unit & 7;
        if (tm < ntm) {
            int aoff[2], boff[2];
#pragma unroll
            for (int c = 0; c < 2; ++c) {
                int g = tm * 128 + rw_[c];
                aoff[c] = s_act[g < nact ? g : nact - 1] * MDIM + q_[c] * 8;
                boff[c] = (tn * 128 + rw_[c]) * MDIM + q_[c] * 8;
            }
            float acc[2][4][4];
#pragma unroll
            for (int mi = 0; mi < 2; ++mi)
#pragma unroll
                for (int ni = 0; ni < 4; ++ni)
#pragma unroll
                    for (int q = 0; q < 4; ++q) acc[mi][ni][q] = 0.f;

            hmma_tile<4>(smb, ks * NSTAGE, NSTAGE, g_Eh, g_Eh, g_Em, g_Bh, g_Bm, g_Bh,
                         aoff, boff, dsw, offA, offB, acc);

            float* dst = ks ? g_xkB : g_xkA;
            int cbase = tn * 128 + wn * 32 + 2 * (lane & 3);
#pragma unroll
            for (int mi = 0; mi < 2; ++mi)
#pragma unroll
                for (int half = 0; half < 2; ++half) {
                    int ridx = wm * 32 + mi * 16 + (lane >> 2) + half * 8;
                    int g = tm * 128 + ridx;
                    if (g < nact) {
                        int row = s_act[g];
                        float* p = dst + row * MDIM + cbase;
#pragma unroll
                        for (int ni = 0; ni < 4; ++ni)
                            *(float2*)(p + ni * 8) = make_float2(acc[mi][ni][half * 2],
                                                                 acc[mi][ni][half * 2 + 1]);
                    }
                }
        }
        gridbar(bar_epoch);

        // ---- elementwise: 4 rows per CTA pass; y-state; softshrink + conv ----
        for (int rr = blockIdx.x * 4; rr < nact; rr += GRID * 4) {
            int quarter = tid >> 7;
            int ridx = rr + quarter;
            bool valid = ridx < nact;
            int row = s_act[valid ? ridx : nact - 1];
            int t = tid & 127;
            int eb = row * MDIM + t * 8;
            float4 xa0 = __ldcg((const float4*)(g_xkA + eb));
            float4 xa1 = __ldcg((const float4*)(g_xkA + eb + 4));
            float4 xb0 = __ldcg((const float4*)(g_xkB + eb));
            float4 xb1 = __ldcg((const float4*)(g_xkB + eb + 4));
            float4 y0 = __ldcg((const float4*)(g_y + eb));
            float4 y1 = __ldcg((const float4*)(g_y + eb + 4));
            float4 s0 = __ldcg((const float4*)(g_s + eb));
            float4 s1 = __ldcg((const float4*)(g_s + eb + 4));
            float xk[8] = {xa0.x + xb0.x, xa0.y + xb0.y, xa0.z + xb0.z, xa0.w + xb0.w,
                           xa1.x + xb1.x, xa1.y + xb1.y, xa1.z + xb1.z, xa1.w + xb1.w};
            float yo[8] = {y0.x, y0.y, y0.z, y0.w, y1.x, y1.y, y1.z, y1.w};
            float so[8] = {s0.x, s0.y, s0.z, s0.w, s1.x, s1.y, s1.z, s1.w};
            float yn[8], vn[8], un[8], dx2 = 0.f, x2 = 0.f;
#pragma unroll
            for (int j = 0; j < 8; ++j) {
                float vo = sshrink(yo[j]);          // v_prev (bit-exact recompute)
                float uo = yo[j] - vo;              // u_prev
                yn[j] = xk[j] + uo;
                vn[j] = sshrink(yn[j]);
                un[j] = yn[j] - vn[j];
                float d = vn[j] - vo;
                dx2 += d * d;
                x2 += vn[j] * vn[j];
            }
#pragma unroll
            for (int o = 16; o; o >>= 1) {
                dx2 += __shfl_xor_sync(0xffffffffu, dx2, o);
                x2 += __shfl_xor_sync(0xffffffffu, x2, o);
            }
            if (lane == 0) { s_red[wrp] = dx2; s_red[16 + wrp] = x2; }
            __syncthreads();
            if (t == 0) {
                float dd = 0.f, xx = 0.f;
#pragma unroll
                for (int i = 0; i < 4; ++i) {
                    dd += s_red[quarter * 4 + i];
                    xx += s_red[16 + quarter * 4 + i];
                }
                s_conv[quarter] = (sqrtf(dd) / sqrtf(xx) < TOLC) ? 1 : 0;  // NaN -> false
            }
            __syncthreads();
            if (valid) {
                if (s_conv[quarter]) {
                    *(float4*)(g_vsol + eb) = make_float4(vn[0], vn[1], vn[2], vn[3]);
                    *(float4*)(g_vsol + eb + 4) = make_float4(vn[4], vn[5], vn[6], vn[7]);
                    __align__(16) __nv_bfloat16 hh[8], mm[8];
#pragma unroll
                    for (int j = 0; j < 8; ++j) split2(vn[j], hh[j], mm[j]);
                    *(uint4*)(g_Vh + eb) = *(uint4*)hh;
                    *(uint4*)(g_Vm + eb) = *(uint4*)mm;
                    if (t == 0) g_flag[row] = 1;
                } else {
                    *(float4*)(g_y + eb) = make_float4(yn[0], yn[1], yn[2], yn[3]);
                    *(float4*)(g_y + eb + 4) = make_float4(yn[4], yn[5], yn[6], yn[7]);
                    __align__(16) __nv_bfloat16 hh[8], mm[8];
#pragma unroll
                    for (int j = 0; j < 8; ++j)
                        split2(so[j] + vn[j] - un[j], hh[j], mm[j]);   // E = s+v-u
                    *(uint4*)(g_Eh + eb) = *(uint4*)hh;
                    *(uint4*)(g_Em + eb) = *(uint4*)mm;
                }
            }
            __syncthreads();
        }
        gridbar(bar_epoch);
    }
}

// ---- decode: CTAs 0-63 HMMA partials of vsol @ w; CTAs 64-127 copy enc ----
__global__ void __launch_bounds__(NTHR, 1) k_decode(float* __restrict__ enc,
                                                    const float* __restrict__ dec) {
    extern __shared__ char sm[];
    const uint32_t smb = smem_u32(sm);
    const int tid = threadIdx.x;
    const int lane = tid & 31, wrp = tid >> 5;
    int bid = blockIdx.x;

    if (bid >= 64) {
        if (enc) {
            const float4* src = (const float4*)g_vsol;
            float4* dst = (float4*)enc;
            for (int i = (bid - 64) * NTHR + tid; i < BATCH * MDIM / 4; i += 64 * NTHR)
                dst[i] = src[i];
        }
        return;
    }
    if (!dec) return;

    int ks = bid >> 5, unit = bid & 31;
    int tm = unit >> 2, tn = unit & 3;
    uint32_t dsw[2];
    int aoff[2], boff[2];
#pragma unroll
    for (int c = 0; c < 2; ++c) {
        int idx = tid + 512 * c;
        int rw = idx >> 3, q = idx & 7;
        dsw[c] = swz((uint32_t)(rw * 128 + q * 16));
        aoff[c] = (tm * 128 + rw) * MDIM + q * 8;
        boff[c] = (tn * 128 + rw) * MDIM + q * 8;
    }
    int wm = wrp >> 2, wn = wrp & 3;
    int rowa = wm * 32 + (lane & 7) + ((lane >> 3) & 1) * 8;
    int qa = lane >> 4;
    uint32_t offA[2];
#pragma unroll
    for (int mi = 0; mi < 2; ++mi)
        offA[mi] = swz((uint32_t)((rowa + mi * 16) * 128 + qa * 16));
    int rowb = wn * 32 + (lane & 7);
    int qb = (lane >> 3) & 1;
    uint32_t offB[4];
#pragma unroll
    for (int ni = 0; ni < 4; ++ni)
        offB[ni] = swz((uint32_t)((rowb + ni * 8) * 128 + qb * 16));

    float acc[2][4][4];
#pragma unroll
    for (int mi = 0; mi < 2; ++mi)
#pragma unroll
        for (int ni = 0; ni < 4; ++ni)
#pragma unroll
            for (int q = 0; q < 4; ++q) acc[mi][ni][q] = 0.f;

    hmma_tile<4>(smb, ks * NSTAGE, NSTAGE, g_Vh, g_Vh, g_Vm, g_Wh, g_Wm, g_Wh,
                 aoff, boff, dsw, offA, offB, acc);

    float* dst = ks ? g_xkB : g_xkA;
    int cbase = tn * 128 + wn * 32 + 2 * (lane & 3);
#pragma unroll
    for (int mi = 0; mi < 2; ++mi)
#pragma unroll
        for (int half = 0; half < 2; ++half) {
            int ridx = wm * 32 + mi * 16 + (lane >> 2) + half * 8;
            int row = tm * 128 + ridx;
            float* p = dst + row * NDIM + cbase;
#pragma unroll
            for (int ni = 0; ni < 4; ++ni) {
                float2 v2 = make_float2(acc[mi][ni][half * 2], acc[mi][ni][half * 2 + 1]);
                *(float2*)(p + ni * 8) = v2;
            }
        }
}

__global__ void k_sum(float* __restrict__ dec) {
    int tid = blockIdx.x * blockDim.x + threadIdx.x, nt = gridDim.x * blockDim.x;
    const float4* pa = (const float4*)g_xkA;
    const float4* pb = (const float4*)g_xkB;
    float4* po = (float4*)dec;
    for (int i = tid; i < BATCH * NDIM / 4; i += nt) {
        float4 a = pa[i], b = pb[i];
        po[i] = make_float4(a.x + b.x, a.y + b.y, a.z + b.z, a.w + b.w);
    }
}

extern "C" void kernel_launch(void* const* d_in, const int* in_sizes, int n_in,
                              void* d_out, int out_size) {
    const float* x = nullptr;
    const float* w = nullptr;
    const float* Minv = nullptr;
    int small[2] = {0, 1}, si = 0;
    for (int i = 0; i < n_in; ++i) {
        if (in_sizes[i] == MDIM * MDIM && !Minv) Minv = (const float*)d_in[i];
        else if (si < 2) small[si++] = i;
    }
    x = (const float*)d_in[small[0]];
    w = (const float*)d_in[small[1]];

    float* out = (float*)d_out;
    float* enc = nullptr;
    float* dec = nullptr;
    if (out_size >= BATCH * MDIM + BATCH * NDIM) { enc = out; dec = out + (size_t)BATCH * MDIM; }
    else if (out_size == BATCH * NDIM) dec = out;
    else enc = out;

    cudaFuncSetAttribute(k_admm, cudaFuncAttributeMaxDynamicSharedMemorySize, SMEM_TOTAL);
    cudaFuncSetAttribute(k_decode, cudaFuncAttributeMaxDynamicSharedMemorySize, SMEM_TOTAL);
    k_init<<<128, 256>>>(x, w);
    k_prep<<<dim3(32, 32), dim3(32, 8)>>>(Minv);
    k_prepw<<<dim3(16, 32), dim3(32, 8)>>>(w);
    k_admm<<<GRID, NTHR, SMEM_TOTAL>>>(x, w);
    k_decode<<<GRID, NTHR, SMEM_TOTAL>>>(enc, dec);
    if (dec) k_sum<<<64, 256>>>(dec);
}

// round 17
// speedup vs baseline: 1.1020x; 1.1020x over previous
#include <cuda_runtime.h>
#include <cuda_bf16.h>
#include <cstdint>

#define BATCH 1024
#define MDIM  1024
#define NDIM  512
#define LAMBD 0.2f
#define TOLC  1e-4f
#define MAX_ITERS 100
#define GRID  128
#define NTHR  512
#define PIPE  2

// dynamic smem layout (bytes)
#define SM_RED   64         // 32 floats
#define SM_CONV  192        // 4 ints
#define SM_SCAN  256        // 16 ints (warp totals)
#define SM_ACT   2560       // 1024 ints
#define SM_A0    8192       // A stage buffers 2 x 32KB
#define SM_B0    73728      // B stage buffers 2 x 32KB
#define SMEM_TOTAL 139264

__device__ __align__(16) float g_s[BATCH * MDIM];            // Adotb (constant)
__device__ __align__(16) float g_y[BATCH * MDIM];            // y = xk + u (pre-shrink)
__device__ __align__(16) float g_vsol[BATCH * MDIM];
__device__ __align__(16) float g_xkA[BATCH * MDIM];
__device__ __align__(16) float g_xkB[BATCH * MDIM];
__device__ __align__(16) __nv_bfloat16 g_Eh[BATCH * MDIM];
__device__ __align__(16) __nv_bfloat16 g_Em[BATCH * MDIM];
__device__ __align__(16) __nv_bfloat16 g_Vh[BATCH * MDIM];   // splits of vsol
__device__ __align__(16) __nv_bfloat16 g_Vm[BATCH * MDIM];
__device__ __align__(16) __nv_bfloat16 g_Bh[MDIM * MDIM];    // B[n][k] = Minv[k][n]
__device__ __align__(16) __nv_bfloat16 g_Bm[MDIM * MDIM];
__device__ __align__(16) __nv_bfloat16 g_Wh[NDIM * MDIM];    // W[n][k] = w[k][n] (decode)
__device__ __align__(16) __nv_bfloat16 g_Wm[NDIM * MDIM];
__device__ __align__(16) __nv_bfloat16 g_Xh[BATCH * NDIM];   // splits of x (Phase A)
__device__ __align__(16) __nv_bfloat16 g_Xm[BATCH * NDIM];
__device__ __align__(16) __nv_bfloat16 g_wh2[MDIM * NDIM];   // splits of w, K-major
__device__ __align__(16) __nv_bfloat16 g_wm2[MDIM * NDIM];
__device__ int g_flag[BATCH];
__device__ int g_arrive[GRID * 32];                           // one 128B line per CTA
__device__ unsigned g_release;

// ---------- helpers ----------
__device__ __forceinline__ uint32_t smem_u32(const void* p) {
    uint32_t a;
    asm("{ .reg .u64 t; cvta.to.shared.u64 t, %1; cvt.u32.u64 %0, t; }" : "=r"(a) : "l"(p));
    return a;
}
__device__ __forceinline__ uint32_t swz(uint32_t o) { return o ^ ((o >> 3) & 0x70); }

__device__ __forceinline__ void cp16(uint32_t d, const void* s) {
    asm volatile("cp.async.cg.shared.global [%0], [%1], 16;" :: "r"(d), "l"(s));
}
__device__ __forceinline__ void cp_commit() { asm volatile("cp.async.commit_group;" ::: "memory"); }
template <int N> __device__ __forceinline__ void cp_wait() {
    asm volatile("cp.async.wait_group %0;" :: "n"(N) : "memory");
}
__device__ __forceinline__ void ldsm_x4(uint32_t& r0, uint32_t& r1, uint32_t& r2,
                                        uint32_t& r3, uint32_t a) {
    asm volatile("ldmatrix.sync.aligned.m8n8.x4.shared.b16 {%0,%1,%2,%3}, [%4];"
                 : "=r"(r0), "=r"(r1), "=r"(r2), "=r"(r3) : "r"(a));
}
__device__ __forceinline__ void ldsm_x2t(uint32_t& r0, uint32_t& r1, uint32_t a) {
    asm volatile("ldmatrix.sync.aligned.m8n8.x2.trans.shared.b16 {%0,%1}, [%2];"
                 : "=r"(r0), "=r"(r1) : "r"(a));
}
__device__ __forceinline__ void mma16816(float d[4], const uint32_t a[4], const uint32_t b[2]) {
    asm volatile(
        "mma.sync.aligned.m16n8k16.row.col.f32.bf16.bf16.f32 "
        "{%0,%1,%2,%3}, {%4,%5,%6,%7}, {%8,%9}, {%0,%1,%2,%3};"
        : "+f"(d[0]), "+f"(d[1]), "+f"(d[2]), "+f"(d[3])
        : "r"(a[0]), "r"(a[1]), "r"(a[2]), "r"(a[3]), "r"(b[0]), "r"(b[1]));
}

// flag-based grid barrier: parallel arrivals (distinct lines) + single release word
__device__ __forceinline__ void gridbar(unsigned& epoch) {
    epoch++;
    __syncthreads();
    const int tid = threadIdx.x;
    if (tid == 0) {
        __threadfence();
        *(volatile int*)&g_arrive[blockIdx.x * 32] = (int)epoch;
    }
    if (blockIdx.x == 0) {
        if (tid < GRID) {
            while (*(volatile int*)&g_arrive[tid * 32] != (int)epoch) {}
        }
        __syncthreads();
        if (tid == 0) {
            __threadfence();
            *(volatile unsigned*)&g_release = epoch;
        }
    }
    if (tid == 0) {
        while (*(volatile unsigned*)&g_release != epoch) {}
        __threadfence();
    }
    __syncthreads();
}

__device__ __forceinline__ float sshrink(float x) {
    return x > LAMBD ? x - LAMBD : (x < -LAMBD ? x + LAMBD : 0.f);
}
__device__ __forceinline__ void split2(float a, __nv_bfloat16& h, __nv_bfloat16& m) {
    h = __float2bfloat16(a);
    m = __float2bfloat16(a - __bfloat162float(h));
}

// init + bf16 splits of x and w (K-major, Phase A) fused
__global__ void k_init(const float* __restrict__ x, const float* __restrict__ w) {
    int tid = blockIdx.x * blockDim.x + threadIdx.x, nt = gridDim.x * blockDim.x;
    float4 z = make_float4(0.f, 0.f, 0.f, 0.f);
    for (int i = tid; i < BATCH * MDIM / 4; i += nt) {
        ((float4*)g_y)[i] = z; ((float4*)g_vsol)[i] = z;
    }
    uint4 z4 = make_uint4(0u, 0u, 0u, 0u);
    for (int i = tid; i < BATCH * MDIM / 8; i += nt) {
        ((uint4*)g_Vh)[i] = z4; ((uint4*)g_Vm)[i] = z4;
    }
    for (int i = tid; i < BATCH; i += nt) g_flag[i] = 0;
    for (int i = tid; i < GRID * 32; i += nt) g_arrive[i] = 0;
    if (tid == 0) g_release = 0u;
    for (int i = tid; i < BATCH * NDIM / 4; i += nt) {
        float4 a = ((const float4*)x)[i];
        float4 b = ((const float4*)w)[i];
        __align__(8) __nv_bfloat16 h[4], m[4];
        split2(a.x, h[0], m[0]); split2(a.y, h[1], m[1]);
        split2(a.z, h[2], m[2]); split2(a.w, h[3], m[3]);
        ((uint2*)g_Xh)[i] = *(uint2*)h; ((uint2*)g_Xm)[i] = *(uint2*)m;
        split2(b.x, h[0], m[0]); split2(b.y, h[1], m[1]);
        split2(b.z, h[2], m[2]); split2(b.w, h[3], m[3]);
        ((uint2*)g_wh2)[i] = *(uint2*)h; ((uint2*)g_wm2)[i] = *(uint2*)m;
    }
}

// transpose + 2-way bf16 split of Minv (1024x1024)
__global__ void k_prep(const float* __restrict__ Minv) {
    __shared__ float t[32][33];
    int tx = threadIdx.x, ty = threadIdx.y, nt = blockIdx.x, kt = blockIdx.y;
#pragma unroll
    for (int i = 0; i < 4; ++i)
        t[ty + 8 * i][tx] = Minv[(kt * 32 + ty + 8 * i) * MDIM + nt * 32 + tx];
    __syncthreads();
#pragma unroll
    for (int i = 0; i < 4; ++i) {
        int n = nt * 32 + ty + 8 * i, k = kt * 32 + tx;
        __nv_bfloat16 h, m;
        split2(t[tx][ty + 8 * i], h, m);
        g_Bh[n * MDIM + k] = h; g_Bm[n * MDIM + k] = m;
    }
}

// transpose + 2-way bf16 split of w (1024x512) -> W[n][k] (for decode)
__global__ void k_prepw(const float* __restrict__ w) {
    __shared__ float t[32][33];
    int tx = threadIdx.x, ty = threadIdx.y, nt = blockIdx.x, kt = blockIdx.y;
#pragma unroll
    for (int i = 0; i < 4; ++i)
        t[ty + 8 * i][tx] = w[(kt * 32 + ty + 8 * i) * NDIM + nt * 32 + tx];
    __syncthreads();
#pragma unroll
    for (int i = 0; i < 4; ++i) {
        int n = nt * 32 + ty + 8 * i, k = kt * 32 + tx;
        __nv_bfloat16 h, m;
        split2(t[tx][ty + 8 * i], h, m);
        g_Wh[n * MDIM + k] = h; g_Wm[n * MDIM + k] = m;
    }
}

// HMMA mainloop: 128x128 tile, 512 threads (16 warps, 32x32 warp tiles),
// nst k128 stages (each = two contiguous 16KB k64 blocks), PIPE=2, one
// __syncthreads per stage. Stage g -> term g>>KSH, k0 = (g & mask)*128.
template <int KSH>
__device__ __forceinline__ void hmma_tile(
    uint32_t smb, int gbase, int nst,
    const __nv_bfloat16* TA0, const __nv_bfloat16* TA1, const __nv_bfloat16* TA2,
    const __nv_bfloat16* TB0, const __nv_bfloat16* TB1, const __nv_bfloat16* TB2,
    const int aoff[4], const int boff[4], const uint32_t dsw[4],
    const uint32_t offA[2], const uint32_t offB[4], float acc[2][4][4]) {
    const __nv_bfloat16* TA[3] = {TA0, TA1, TA2};
    const __nv_bfloat16* TB[3] = {TB0, TB1, TB2};
    const int KM = (1 << KSH) - 1;
    // prologue: stage gbase -> buf 0
    {
        int g = gbase, t2 = g >> KSH, k2 = (g & KM) * 128;
        uint32_t ab = smb + SM_A0, bb = smb + SM_B0;
#pragma unroll
        for (int c = 0; c < 4; ++c) {
            cp16(ab + dsw[c], TA[t2] + aoff[c] + k2);
            cp16(bb + dsw[c], TB[t2] + boff[c] + k2);
        }
        cp_commit();
    }
    for (int s = 0; s < nst; ++s) {
        cp_wait<0>();
        __syncthreads();
        if (s + 1 < nst) {
            int nb = (s + 1) & 1;
            int g = gbase + s + 1, t2 = g >> KSH, k2 = (g & KM) * 128;
            uint32_t ab = smb + SM_A0 + nb * 32768, bb = smb + SM_B0 + nb * 32768;
#pragma unroll
            for (int c = 0; c < 4; ++c) {
                cp16(ab + dsw[c], TA[t2] + aoff[c] + k2);
                cp16(bb + dsw[c], TB[t2] + boff[c] + k2);
            }
            cp_commit();
        }
        int buf = s & 1;
        uint32_t Ab = smb + SM_A0 + buf * 32768;
        uint32_t Bb = smb + SM_B0 + buf * 32768;
#pragma unroll
        for (int kk = 0; kk < 8; ++kk) {
            uint32_t sub = (uint32_t)((kk & 4) << 12);   // k64 sub-block: +16KB
            uint32_t kx = (uint32_t)((kk & 3) << 5);
            uint32_t af[2][4], bf[4][2];
#pragma unroll
            for (int mi = 0; mi < 2; ++mi)
                ldsm_x4(af[mi][0], af[mi][1], af[mi][2], af[mi][3],
                        Ab + sub + (offA[mi] ^ kx));
#pragma unroll
            for (int ni = 0; ni < 4; ++ni)
                ldsm_x2t(bf[ni][0], bf[ni][1], Bb + sub + (offB[ni] ^ kx));
#pragma unroll
            for (int mi = 0; mi < 2; ++mi)
#pragma unroll
                for (int ni = 0; ni < 4; ++ni)
                    mma16816(acc[mi][ni], af[mi], bf[ni]);
        }
    }
    cp_wait<0>();
}

__global__ void __launch_bounds__(NTHR, 1)
k_admm(const float* __restrict__ x, const float* __restrict__ w) {
    extern __shared__ char sm[];
    const uint32_t smb = smem_u32(sm);
    const int tid = threadIdx.x;
    const int lane = tid & 31, wrp = tid >> 5;
    unsigned bar_epoch = 0;

    int* s_scan = (int*)(sm + SM_SCAN);
    int* s_act = (int*)(sm + SM_ACT);
    float* s_red = (float*)(sm + SM_RED);
    int* s_conv = (int*)(sm + SM_CONV);

    // per-lane ldmatrix offsets (within a 16KB k64 block)
    const int wm = wrp >> 2, wn = wrp & 3;
    const int rowa = wm * 32 + (lane & 7) + ((lane >> 3) & 1) * 8;
    const int qa = lane >> 4;
    uint32_t offA[2];
#pragma unroll
    for (int mi = 0; mi < 2; ++mi)
        offA[mi] = swz((uint32_t)((rowa + mi * 16) * 128 + qa * 16));
    const int rowb = wn * 32 + (lane & 7);
    const int qb = (lane >> 3) & 1;
    uint32_t offB[4];
#pragma unroll
    for (int ni = 0; ni < 4; ++ni)
        offB[ni] = swz((uint32_t)((rowb + ni * 8) * 128 + qb * 16));
    // chunk-load mapping: 4 chunks/thread/operand per k128 stage
    uint32_t dsw[4];
    int rw_[4], ksub_[4];
#pragma unroll
    for (int c = 0; c < 4; ++c) {
        int sub = c >> 1;
        int idx = tid + 512 * (c & 1);
        int rw = idx >> 3, q = idx & 7;
        rw_[c] = rw;
        ksub_[c] = sub * 64 + q * 8;                 // k offset within the stage
        dsw[c] = (uint32_t)(sub * 16384) + swz((uint32_t)(rw * 128 + q * 16));
    }

    // ===== Phase A: s = x @ w^T via HMMA (3 terms, K=512, 2-way K-split) =====
    {
        int unit = blockIdx.x & 63, ks = blockIdx.x >> 6;
        int tm = unit >> 3, tn = unit & 7;
        int aoff[4], boff[4];
#pragma unroll
        for (int c = 0; c < 4; ++c) {
            aoff[c] = (tm * 128 + rw_[c]) * NDIM + ksub_[c];
            boff[c] = (tn * 128 + rw_[c]) * NDIM + ksub_[c];
        }
        float acc[2][4][4];
#pragma unroll
        for (int mi = 0; mi < 2; ++mi)
#pragma unroll
            for (int ni = 0; ni < 4; ++ni)
#pragma unroll
                for (int q = 0; q < 4; ++q) acc[mi][ni][q] = 0.f;

        hmma_tile<2>(smb, ks * 6, 6, g_Xh, g_Xh, g_Xm, g_wh2, g_wm2, g_wh2,
                     aoff, boff, dsw, offA, offB, acc);

        float* dst = ks ? g_xkB : g_xkA;
        int cbase = tn * 128 + wn * 32 + 2 * (lane & 3);
#pragma unroll
        for (int mi = 0; mi < 2; ++mi)
#pragma unroll
            for (int half = 0; half < 2; ++half) {
                int row = tm * 128 + wm * 32 + mi * 16 + (lane >> 2) + half * 8;
                float* p = dst + row * MDIM + cbase;
#pragma unroll
                for (int ni = 0; ni < 4; ++ni)
                    *(float2*)(p + ni * 8) = make_float2(acc[mi][ni][half * 2],
                                                         acc[mi][ni][half * 2 + 1]);
            }
    }
    gridbar(bar_epoch);
    // sum partials -> s, initial E splits (v=u=0 -> E=s)
    {
        for (int i = blockIdx.x * NTHR + tid; i < BATCH * MDIM / 4; i += GRID * NTHR) {
            float4 a = __ldcg((const float4*)g_xkA + i);
            float4 b = __ldcg((const float4*)g_xkB + i);
            float4 sv = make_float4(a.x + b.x, a.y + b.y, a.z + b.z, a.w + b.w);
            ((float4*)g_s)[i] = sv;
            __align__(8) __nv_bfloat16 h[4], m[4];
            split2(sv.x, h[0], m[0]); split2(sv.y, h[1], m[1]);
            split2(sv.z, h[2], m[2]); split2(sv.w, h[3], m[3]);
            ((uint2*)g_Eh)[i] = *(uint2*)h;
            ((uint2*)g_Em)[i] = *(uint2*)m;
        }
    }
    gridbar(bar_epoch);

    // ===== ADMM loop =====
    for (int it = 0; it < MAX_ITERS; ++it) {
        // shuffle-based ordered compaction of active rows (2 flags/thread)
        int fl[2], cnt = 0;
#pragma unroll
        for (int j = 0; j < 2; ++j) { fl[j] = g_flag[tid * 2 + j]; cnt += (fl[j] == 0); }
        int inc = cnt;
#pragma unroll
        for (int o = 1; o < 32; o <<= 1) {
            int nv = __shfl_up_sync(0xffffffffu, inc, o);
            if (lane >= o) inc += nv;
        }
        if (lane == 31) s_scan[wrp] = inc;
        __syncthreads();
        if (wrp == 0) {
            int v = (lane < 16) ? s_scan[lane] : 0;
#pragma unroll
            for (int o = 1; o < 16; o <<= 1) {
                int nv = __shfl_up_sync(0xffffffffu, v, o);
                if (lane >= o) v += nv;
            }
            if (lane < 16) s_scan[lane] = v;
        }
        __syncthreads();
        int base = (wrp ? s_scan[wrp - 1] : 0) + inc - cnt;
#pragma unroll
        for (int j = 0; j < 2; ++j)
            if (!fl[j]) s_act[base++] = tid * 2 + j;
        int nact = s_scan[15];
        __syncthreads();
        if (nact == 0) break;
        int ntm = (nact + 127) >> 7;

        // ---- HMMA GEMM: xk partials over 3 bf16-split terms (hh, hm, mh) ----
        int unit = blockIdx.x & 63, ks = blockIdx.x >> 6;
        int tm = unit >> 3, tn = unit & 7;
        if (tm < ntm) {
            int aoff[4], boff[4];
#pragma unroll
            for (int c = 0; c < 4; ++c) {
                int g = tm * 128 + rw_[c];
                aoff[c] = s_act[g < nact ? g : nact - 1] * MDIM + ksub_[c];
                boff[c] = (tn * 128 + rw_[c]) * MDIM + ksub_[c];
            }
            float acc[2][4][4];
#pragma unroll
            for (int mi = 0; mi < 2; ++mi)
#pragma unroll
                for (int ni = 0; ni < 4; ++ni)
#pragma unroll
                    for (int q = 0; q < 4; ++q) acc[mi][ni][q] = 0.f;

            hmma_tile<3>(smb, ks * 12, 12, g_Eh, g_Eh, g_Em, g_Bh, g_Bm, g_Bh,
                         aoff, boff, dsw, offA, offB, acc);

            float* dst = ks ? g_xkB : g_xkA;
            int cbase = tn * 128 + wn * 32 + 2 * (lane & 3);
#pragma unroll
            for (int mi = 0; mi < 2; ++mi)
#pragma unroll
                for (int half = 0; half < 2; ++half) {
                    int ridx = wm * 32 + mi * 16 + (lane >> 2) + half * 8;
                    int g = tm * 128 + ridx;
                    if (g < nact) {
                        int row = s_act[g];
                        float* p = dst + row * MDIM + cbase;
#pragma unroll
                        for (int ni = 0; ni < 4; ++ni)
                            *(float2*)(p + ni * 8) = make_float2(acc[mi][ni][half * 2],
                                                                 acc[mi][ni][half * 2 + 1]);
                    }
                }
        }
        gridbar(bar_epoch);

        // ---- elementwise: 4 rows per CTA pass; y-state; softshrink + conv ----
        for (int rr = blockIdx.x * 4; rr < nact; rr += GRID * 4) {
            int quarter = tid >> 7;
            int ridx = rr + quarter;
            bool valid = ridx < nact;
            int row = s_act[valid ? ridx : nact - 1];
            int t = tid & 127;
            int eb = row * MDIM + t * 8;
            float4 xa0 = __ldcg((const float4*)(g_xkA + eb));
            float4 xa1 = __ldcg((const float4*)(g_xkA + eb + 4));
            float4 xb0 = __ldcg((const float4*)(g_xkB + eb));
            float4 xb1 = __ldcg((const float4*)(g_xkB + eb + 4));
            float4 y0 = __ldcg((const float4*)(g_y + eb));
            float4 y1 = __ldcg((const float4*)(g_y + eb + 4));
            float4 s0 = __ldcg((const float4*)(g_s + eb));
            float4 s1 = __ldcg((const float4*)(g_s + eb + 4));
            float xk[8] = {xa0.x + xb0.x, xa0.y + xb0.y, xa0.z + xb0.z, xa0.w + xb0.w,
                           xa1.x + xb1.x, xa1.y + xb1.y, xa1.z + xb1.z, xa1.w + xb1.w};
            float yo[8] = {y0.x, y0.y, y0.z, y0.w, y1.x, y1.y, y1.z, y1.w};
            float so[8] = {s0.x, s0.y, s0.z, s0.w, s1.x, s1.y, s1.z, s1.w};
            float yn[8], vn[8], un[8], dx2 = 0.f, x2 = 0.f;
#pragma unroll
            for (int j = 0; j < 8; ++j) {
                float vo = sshrink(yo[j]);          // v_prev (bit-exact recompute)
                float uo = yo[j] - vo;              // u_prev
                yn[j] = xk[j] + uo;
                vn[j] = sshrink(yn[j]);
                un[j] = yn[j] - vn[j];
                float d = vn[j] - vo;
                dx2 += d * d;
                x2 += vn[j] * vn[j];
            }
#pragma unroll
            for (int o = 16; o; o >>= 1) {
                dx2 += __shfl_xor_sync(0xffffffffu, dx2, o);
                x2 += __shfl_xor_sync(0xffffffffu, x2, o);
            }
            if (lane == 0) { s_red[wrp] = dx2; s_red[16 + wrp] = x2; }
            __syncthreads();
            if (t == 0) {
                float dd = 0.f, xx = 0.f;
#pragma unroll
                for (int i = 0; i < 4; ++i) {
                    dd += s_red[quarter * 4 + i];
                    xx += s_red[16 + quarter * 4 + i];
                }
                s_conv[quarter] = (sqrtf(dd) / sqrtf(xx) < TOLC) ? 1 : 0;  // NaN -> false
            }
            __syncthreads();
            if (valid) {
                if (s_conv[quarter]) {
                    *(float4*)(g_vsol + eb) = make_float4(vn[0], vn[1], vn[2], vn[3]);
                    *(float4*)(g_vsol + eb + 4) = make_float4(vn[4], vn[5], vn[6], vn[7]);
                    __align__(16) __nv_bfloat16 hh[8], mm[8];
#pragma unroll
                    for (int j = 0; j < 8; ++j) split2(vn[j], hh[j], mm[j]);
                    *(uint4*)(g_Vh + eb) = *(uint4*)hh;
                    *(uint4*)(g_Vm + eb) = *(uint4*)mm;
                    if (t == 0) g_flag[row] = 1;
                } else {
                    *(float4*)(g_y + eb) = make_float4(yn[0], yn[1], yn[2], yn[3]);
                    *(float4*)(g_y + eb + 4) = make_float4(yn[4], yn[5], yn[6], yn[7]);
                    __align__(16) __nv_bfloat16 hh[8], mm[8];
#pragma unroll
                    for (int j = 0; j < 8; ++j)
                        split2(so[j] + vn[j] - un[j], hh[j], mm[j]);   // E = s+v-u
                    *(uint4*)(g_Eh + eb) = *(uint4*)hh;
                    *(uint4*)(g_Em + eb) = *(uint4*)mm;
                }
            }
            __syncthreads();
        }
        gridbar(bar_epoch);
    }
}

// ---- decode: CTAs 0-63 HMMA partials of vsol @ w; CTAs 64-127 copy enc ----
__global__ void __launch_bounds__(NTHR, 1) k_decode(float* __restrict__ enc,
                                                    const float* __restrict__ dec) {
    extern __shared__ char sm[];
    const uint32_t smb = smem_u32(sm);
    const int tid = threadIdx.x;
    const int lane = tid & 31, wrp = tid >> 5;
    int bid = blockIdx.x;

    if (bid >= 64) {
        if (enc) {
            const float4* src = (const float4*)g_vsol;
            float4* dst = (float4*)enc;
            for (int i = (bid - 64) * NTHR + tid; i < BATCH * MDIM / 4; i += 64 * NTHR)
                dst[i] = src[i];
        }
        return;
    }
    if (!dec) return;

    int ks = bid >> 5, unit = bid & 31;
    int tm = unit >> 2, tn = unit & 3;
    uint32_t dsw[4];
    int aoff[4], boff[4];
#pragma unroll
    for (int c = 0; c < 4; ++c) {
        int sub = c >> 1;
        int idx = tid + 512 * (c & 1);
        int rw = idx >> 3, q = idx & 7;
        int ksub = sub * 64 + q * 8;
        dsw[c] = (uint32_t)(sub * 16384) + swz((uint32_t)(rw * 128 + q * 16));
        aoff[c] = (tm * 128 + rw) * MDIM + ksub;
        boff[c] = (tn * 128 + rw) * MDIM + ksub;
    }
    int wm = wrp >> 2, wn = wrp & 3;
    int rowa = wm * 32 + (lane & 7) + ((lane >> 3) & 1) * 8;
    int qa = lane >> 4;
    uint32_t offA[2];
#pragma unroll
    for (int mi = 0; mi < 2; ++mi)
        offA[mi] = swz((uint32_t)((rowa + mi * 16) * 128 + qa * 16));
    int rowb = wn * 32 + (lane & 7);
    int qb = (lane >> 3) & 1;
    uint32_t offB[4];
#pragma unroll
    for (int ni = 0; ni < 4; ++ni)
        offB[ni] = swz((uint32_t)((rowb + ni * 8) * 128 + qb * 16));

    float acc[2][4][4];
#pragma unroll
    for (int mi = 0; mi < 2; ++mi)
#pragma unroll
        for (int ni = 0; ni < 4; ++ni)
#pragma unroll
            for (int q = 0; q < 4; ++q) acc[mi][ni][q] = 0.f;

    hmma_tile<3>(smb, ks * 12, 12, g_Vh, g_Vh, g_Vm, g_Wh, g_Wm, g_Wh,
                 aoff, boff, dsw, offA, offB, acc);

    float* dst = ks ? g_xkB : g_xkA;
    int cbase = tn * 128 + wn * 32 + 2 * (lane & 3);
#pragma unroll
    for (int mi = 0; mi < 2; ++mi)
#pragma unroll
        for (int half = 0; half < 2; ++half) {
            int ridx = wm * 32 + mi * 16 + (lane >> 2) + half * 8;
            int row = tm * 128 + ridx;
            float* p = dst + row * NDIM + cbase;
#pragma unroll
            for (int ni = 0; ni < 4; ++ni) {
                float2 v2 = make_float2(acc[mi][ni][half * 2], acc[mi][ni][half * 2 + 1]);
                *(float2*)(p + ni * 8) = v2;
            }
        }
}

__global__ void k_sum(float* __restrict__ dec) {
    int tid = blockIdx.x * blockDim.x + threadIdx.x, nt = gridDim.x * blockDim.x;
    const float4* pa = (const float4*)g_xkA;
    const float4* pb = (const float4*)g_xkB;
    float4* po = (float4*)dec;
    for (int i = tid; i < BATCH * NDIM / 4; i += nt) {
        float4 a = pa[i], b = pb[i];
        po[i] = make_float4(a.x + b.x, a.y + b.y, a.z + b.z, a.w + b.w);
    }
}

extern "C" void kernel_launch(void* const* d_in, const int* in_sizes, int n_in,
                              void* d_out, int out_size) {
    const float* x = nullptr;
    const float* w = nullptr;
    const float* Minv = nullptr;
    int small[2] = {0, 1}, si = 0;
    for (int i = 0; i < n_in; ++i) {
        if (in_sizes[i] == MDIM * MDIM && !Minv) Minv = (const float*)d_in[i];
        else if (si < 2) small[si++] = i;
    }
    x = (const float*)d_in[small[0]];
    w = (const float*)d_in[small[1]];

    float* out = (float*)d_out;
    float* enc = nullptr;
    float* dec = nullptr;
    if (out_size >= BATCH * MDIM + BATCH * NDIM) { enc = out; dec = out + (size_t)BATCH * MDIM; }
    else if (out_size == BATCH * NDIM) dec = out;
    else enc = out;

    cudaFuncSetAttribute(k_admm, cudaFuncAttributeMaxDynamicSharedMemorySize, SMEM_TOTAL);
    cudaFuncSetAttribute(k_decode, cudaFuncAttributeMaxDynamicSharedMemorySize, SMEM_TOTAL);
    k_init<<<128, 256>>>(x, w);
    k_prep<<<dim3(32, 32), dim3(32, 8)>>>(Minv);
    k_prepw<<<dim3(16, 32), dim3(32, 8)>>>(w);
    k_admm<<<GRID, NTHR, SMEM_TOTAL>>>(x, w);
    k_decode<<<GRID, NTHR, SMEM_TOTAL>>>(enc, dec);
    if (dec) k_sum<<<64, 256>>>(dec);
}